// round 4
// baseline (speedup 1.0000x reference)
#include <cuda_runtime.h>
#include <cstdint>

#define T_STEPS 15
#define C_IN    6
#define HW_IN   256
#define OC1     30
#define H2      128
#define W2      128
#define OC2     250
#define SP_H    130
#define SP_W    130
#define THR1    15.0f
#define THR2    10.0f
#define NPIX    (H2*W2)            /* 16384 */
#define NCHW    (OC2*NPIX)         /* 4,096,000 */
#define NOUT1   (T_STEPS*OC2*NPIX) /* 61,440,000 */
#define NSP     (T_STEPS*OC1*SP_H*SP_W) /* 7,605,000 */
#define NPART   2048

// ---------------- scratch (static __device__: no allocations allowed) ----------
__device__ float          g_sp[NSP];          // pooled+padded layer-1 spikes
__device__ int            g_amax[T_STEPS*NPIX];
__device__ int            g_clamp[T_STEPS*NPIX];
__device__ int            g_win[NPIX];
__device__ int            g_spiked[NPIX];
__device__ float          g_values[NCHW];
__device__ unsigned char  g_nspk[NCHW];
__device__ float          g_total[NCHW];
__device__ int            g_maxv;
__device__ float          g_pval[NPART];
__device__ int            g_pidx[NPART];

// ---------------- packed fp32x2 helpers (Blackwell) ----------------------------
__device__ __forceinline__ void fma2(unsigned long long &d, unsigned long long a,
                                     unsigned long long b) {
    asm("fma.rn.f32x2 %0, %1, %2, %0;" : "+l"(d) : "l"(a), "l"(b));
}
__device__ __forceinline__ unsigned long long pack2(float x, float y) {
    unsigned long long r;
    asm("mov.b64 %0, {%1, %2};" : "=l"(r) : "f"(x), "f"(y));
    return r;
}
__device__ __forceinline__ void unpack2(unsigned long long v, float &x, float &y) {
    asm("mov.b64 {%0, %1}, %2;" : "=f"(x), "=f"(y) : "l"(v));
}

// ---------------- init ---------------------------------------------------------
__global__ void zero_kernel() {
    int i = blockIdx.x * 256 + threadIdx.x;
    if (i == 0) g_maxv = 0;
    if (i < NSP) g_sp[i] = 0.0f;
}

// ---------------- conv1 + fire(15) + maxpool2 + pad1 ---------------------------
// grid (64 tiles, 3 oc-groups of 10, 15 t), block (32,8).
// Each thread: one pooled pixel = max-fire over its 2x2 conv quad, for 10 oc
// (5 packed f32x2 channel pairs).
__global__ __launch_bounds__(256, 2)
void conv1_kernel(const float* __restrict__ x, const float* __restrict__ w1) {
    const int t    = blockIdx.z;
    const int ocg  = blockIdx.y;                 // oc base = ocg*10
    const int tile = blockIdx.x;                 // 16 rows x 4 cols of tiles
    const int PH0  = (tile >> 2) * 8;            // pooled tile: 8 high
    const int PW0  = (tile & 3) * 32;            // 32 wide
    const int tx = threadIdx.x, ty = threadIdx.y;
    const int tid = ty * 32 + tx;

    __shared__ float  xs[C_IN][20][69];
    __shared__ float2 sw1[C_IN * 25 * 5];

    // weights: pair p -> (oc0, oc0+1)
    for (int i = tid; i < C_IN * 25 * 5; i += 256) {
        int p = i % 5, k = (i / 5) % 25, ic = i / 125;
        int oc0 = ocg * 10 + 2 * p;
        sw1[i] = make_float2(w1[(oc0 * C_IN + ic) * 25 + k],
                             w1[((oc0 + 1) * C_IN + ic) * 25 + k]);
    }
    // x tile (20 rows x 68 cols per ic), zero-padded at image border (pad=2)
    const int GR0 = 2 * PH0 - 2;
    const int GC0 = 2 * PW0 - 2;
    for (int i = tid; i < C_IN * 20 * 68; i += 256) {
        int cc = i % 68, rr = (i / 68) % 20, ic = i / (68 * 20);
        int gr = GR0 + rr, gc = GC0 + cc;
        float v = 0.0f;
        if (gr >= 0 && gr < HW_IN && gc >= 0 && gc < HW_IN)
            v = x[((size_t)(t * C_IN + ic) * HW_IN + gr) * HW_IN + gc];
        xs[ic][rr][cc] = v;
    }
    __syncthreads();

    unsigned long long acc[5][4];
#pragma unroll
    for (int p = 0; p < 5; p++)
#pragma unroll
        for (int q = 0; q < 4; q++) acc[p][q] = 0ULL;

    const int rb = 2 * ty;
    const int cb = 2 * tx;

#pragma unroll
    for (int ic = 0; ic < C_IN; ic++) {
        unsigned long long cur[6], nxt[6];
#pragma unroll
        for (int j = 0; j < 6; j++) {
            float v = xs[ic][rb][cb + j];
            cur[j] = pack2(v, v);
        }
#pragma unroll
        for (int kh = 0; kh < 5; kh++) {
#pragma unroll
            for (int j = 0; j < 6; j++) {
                float v = xs[ic][rb + kh + 1][cb + j];
                nxt[j] = pack2(v, v);
            }
#pragma unroll
            for (int kw = 0; kw < 5; kw++) {
                const float2* wr = &sw1[(ic * 25 + kh * 5 + kw) * 5];
#pragma unroll
                for (int p = 0; p < 5; p++) {
                    unsigned long long wp =
                        *reinterpret_cast<const unsigned long long*>(&wr[p]);
                    fma2(acc[p][0], wp, cur[kw]);
                    fma2(acc[p][1], wp, cur[kw + 1]);
                    fma2(acc[p][2], wp, nxt[kw]);
                    fma2(acc[p][3], wp, nxt[kw + 1]);
                }
            }
#pragma unroll
            for (int j = 0; j < 6; j++) cur[j] = nxt[j];
        }
    }

    const int ph = PH0 + ty, pw = PW0 + tx;
#pragma unroll
    for (int p = 0; p < 5; p++) {
        float a0, b0, a1, b1, a2, b2, a3, b3;
        unpack2(acc[p][0], a0, b0);
        unpack2(acc[p][1], a1, b1);
        unpack2(acc[p][2], a2, b2);
        unpack2(acc[p][3], a3, b3);
        float s0 = (a0 > THR1 || a1 > THR1 || a2 > THR1 || a3 > THR1) ? 1.0f : 0.0f;
        float s1 = (b0 > THR1 || b1 > THR1 || b2 > THR1 || b3 > THR1) ? 1.0f : 0.0f;
        int oc0 = ocg * 10 + 2 * p;
        g_sp[((size_t)(t * OC1 + oc0) * SP_H + ph + 1) * SP_W + pw + 1] = s0;
        g_sp[((size_t)(t * OC1 + oc0 + 1) * SP_H + ph + 1) * SP_W + pw + 1] = s1;
    }
}

// ---------------- conv2 + fire(10) ---------------------------------------------
// grid (16 tiles, 25 oc-groups of 10, 15 t), block (32,8).
// Thread computes 4 output rows x 1 col for 10 oc (5 f32x2 pairs).
// Zero-input-channel tiles are skipped (early timesteps have no spikes).
__global__ __launch_bounds__(256, 2)
void conv2_kernel(const float* __restrict__ w2, float* __restrict__ out_pot) {
    const int t    = blockIdx.z;
    const int ocg  = blockIdx.y;
    const int tile = blockIdx.x;                 // 4x4 tiles of 32x32
    const int H0   = (tile >> 2) * 32;
    const int W0   = (tile & 3) * 32;
    const int tx = threadIdx.x, ty = threadIdx.y;
    const int tid = ty * 32 + tx;
    const int base = ocg * 10;

    __shared__ float  xs[6][34][35];
    __shared__ float2 sw2[30 * 9 * 5];
    __shared__ int    flags[6];

    for (int i = tid; i < 30 * 9 * 5; i += 256) {
        int p = i % 5, k = (i / 5) % 9, ic = i / 45;
        int oc0 = base + 2 * p;
        sw2[i] = make_float2(w2[(oc0 * 30 + ic) * 9 + k],
                             w2[((oc0 + 1) * 30 + ic) * 9 + k]);
    }

    unsigned long long acc[5][4];
#pragma unroll
    for (int p = 0; p < 5; p++)
#pragma unroll
        for (int q = 0; q < 4; q++) acc[p][q] = 0ULL;

    for (int ch = 0; ch < 5; ch++) {            // 5 chunks of 6 input channels
        __syncthreads();
        if (tid < 6) flags[tid] = 0;
        __syncthreads();
        for (int i = tid; i < 6 * 34 * 34; i += 256) {
            int cc = i % 34, rr = (i / 34) % 34, e = i / (34 * 34);
            int ic = ch * 6 + e;
            float v = g_sp[((size_t)(t * OC1 + ic) * SP_H + H0 + rr) * SP_W + W0 + cc];
            xs[e][rr][cc] = v;
            if (v != 0.0f) flags[e] = 1;        // benign race, all write 1
        }
        __syncthreads();
#pragma unroll
        for (int e = 0; e < 6; e++) {
            if (!flags[e]) continue;            // uniform branch
            int ic = ch * 6 + e;
            unsigned long long xx[6][3];
#pragma unroll
            for (int rr = 0; rr < 6; rr++)
#pragma unroll
                for (int kw = 0; kw < 3; kw++) {
                    float v = xs[e][ty * 4 + rr][tx + kw];
                    xx[rr][kw] = pack2(v, v);
                }
#pragma unroll
            for (int kh = 0; kh < 3; kh++)
#pragma unroll
                for (int kw = 0; kw < 3; kw++) {
                    const float2* wr = &sw2[(ic * 9 + kh * 3 + kw) * 5];
#pragma unroll
                    for (int p = 0; p < 5; p++) {
                        unsigned long long wp =
                            *reinterpret_cast<const unsigned long long*>(&wr[p]);
                        fma2(acc[p][0], wp, xx[0 + kh][kw]);
                        fma2(acc[p][1], wp, xx[1 + kh][kw]);
                        fma2(acc[p][2], wp, xx[2 + kh][kw]);
                        fma2(acc[p][3], wp, xx[3 + kh][kw]);
                    }
                }
        }
    }

#pragma unroll
    for (int p = 0; p < 5; p++) {
        int oc0 = base + 2 * p;
#pragma unroll
        for (int r = 0; r < 4; r++) {
            float lo, hi;
            unpack2(acc[p][r], lo, hi);
            lo = (lo > THR2) ? lo : 0.0f;       // fire(pot, 10)
            hi = (hi > THR2) ? hi : 0.0f;
            int row = H0 + ty * 4 + r, col = W0 + tx;
            out_pot[((size_t)(t * OC2 + oc0) * H2 + row) * W2 + col] = lo;
            out_pot[((size_t)(t * OC2 + oc0 + 1) * H2 + row) * W2 + col] = hi;
        }
    }
}

// ---------------- pointwise inhibition -----------------------------------------
// pass a: per (t,hw): channel argmax (first max) + "any spike" flag
__global__ void inh_a_kernel(const float* __restrict__ pot) {
    int id = blockIdx.x * blockDim.x + threadIdx.x;
    if (id >= T_STEPS * NPIX) return;
    int t = id / NPIX, hw = id % NPIX;
    const float* p = pot + (size_t)t * NCHW + hw;
    float m = p[0];
    int a = 0;
    for (int c = 1; c < OC2; c++) {
        float v = p[(size_t)c * NPIX];
        if (v > m) { m = v; a = c; }            // strict > keeps first max (jnp.argmax)
    }
    g_amax[id]  = a;
    g_clamp[id] = (m > 0.0f) ? 1 : 0;
}

// pass b: per hw: first_t, winner channel, spiked-at-last-t
__global__ void inh_b_kernel() {
    int hw = blockIdx.x * blockDim.x + threadIdx.x;
    if (hw >= NPIX) return;
    int nspk = 0;
    for (int t = 0; t < T_STEPS; t++) nspk += g_clamp[t * NPIX + hw];
    int ft = T_STEPS - nspk;
    if (ft < 0) ft = 0;
    if (ft > T_STEPS - 1) ft = T_STEPS - 1;
    g_win[hw]    = g_amax[ft * NPIX + hw];
    g_spiked[hw] = g_clamp[(T_STEPS - 1) * NPIX + hw];
}

// apply: zero all channels except winner (if spiked at last t); emit spk=sign(pot)
__global__ void apply_kernel(float* __restrict__ pot, float* __restrict__ spk) {
    size_t i = (size_t)blockIdx.x * blockDim.x + threadIdx.x;
    if (i >= (size_t)NOUT1) return;
    int hw = (int)(i & (NPIX - 1));
    int c  = (int)((i >> 14) % OC2);
    float v = pot[i];
    bool keep = (g_win[hw] == c) && (g_spiked[hw] != 0);
    float pv = keep ? v : 0.0f;
    pot[i] = pv;
    spk[i] = (pv > 0.0f) ? 1.0f : 0.0f;
}

// ---------------- k-winners ----------------------------------------------------
// per (c,h,w): nspikes, pot at first_t, global max of "values"
__global__ void stats_kernel(const float* __restrict__ pot) {
    int i = blockIdx.x * blockDim.x + threadIdx.x;
    float local = 0.0f;
    if (i < NCHW) {
        int ns = 0;
#pragma unroll
        for (int t = 0; t < T_STEPS; t++)
            ns += (pot[(size_t)t * NCHW + i] > 0.0f) ? 1 : 0;
        int ft = T_STEPS - ns;
        if (ft < 0) ft = 0;
        if (ft > T_STEPS - 1) ft = T_STEPS - 1;
        float val = pot[(size_t)ft * NCHW + i];
        g_values[i] = val;
        g_nspk[i] = (unsigned char)ns;
        local = val;                            // nspk==0 => val==0, safe for max
    }
    __shared__ float sm[256];
    sm[threadIdx.x] = local;
    __syncthreads();
    for (int s = 128; s > 0; s >>= 1) {
        if (threadIdx.x < s) sm[threadIdx.x] = fmaxf(sm[threadIdx.x], sm[threadIdx.x + s]);
        __syncthreads();
    }
    if (threadIdx.x == 0) atomicMax(&g_maxv, __float_as_int(sm[0]));  // vals >= 0
}

__global__ void total_kernel() {
    int i = blockIdx.x * blockDim.x + threadIdx.x;
    if (i >= NCHW) return;
    float v = 15.0f * __int_as_float(g_maxv);
    g_total[i] = (float)g_nspk[i] * (g_values[i] + v);
}

// stage-1 argmax with first-flat-index tie-break
__global__ void argmax1_kernel() {
    int b = blockIdx.x;
    int start = b * (NCHW / NPART);             // 2000 elems per block, exact cover
    float bv = -1.0f;
    int bi = 0;
    for (int i = start + threadIdx.x; i < start + (NCHW / NPART); i += 256) {
        float v = g_total[i];
        if (v > bv) { bv = v; bi = i; }         // ascending i: first max kept
    }
    __shared__ float sv[256];
    __shared__ int   si[256];
    sv[threadIdx.x] = bv;
    si[threadIdx.x] = bi;
    __syncthreads();
    for (int s = 128; s > 0; s >>= 1) {
        if (threadIdx.x < s) {
            float v2 = sv[threadIdx.x + s];
            int i2 = si[threadIdx.x + s];
            if (v2 > sv[threadIdx.x] ||
                (v2 == sv[threadIdx.x] && i2 < si[threadIdx.x])) {
                sv[threadIdx.x] = v2;
                si[threadIdx.x] = i2;
            }
        }
        __syncthreads();
    }
    if (threadIdx.x == 0) { g_pval[b] = sv[0]; g_pidx[b] = si[0]; }
}

// stage-2: final argmax, write winner k, lateral inhibition zero-out
__global__ void argmax2_kernel(float* __restrict__ out_win, int k) {
    int tid = threadIdx.x;
    float bv = -1.0f;
    int bi = 0;
    for (int i = tid; i < NPART; i += 256) {
        float v = g_pval[i];
        int idx = g_pidx[i];
        if (v > bv || (v == bv && idx < bi)) { bv = v; bi = idx; }
    }
    __shared__ float sv[256];
    __shared__ int   si[256];
    __shared__ int   wc, wh, ww, wvalid;
    sv[tid] = bv;
    si[tid] = bi;
    __syncthreads();
    for (int s = 128; s > 0; s >>= 1) {
        if (tid < s) {
            float v2 = sv[tid + s];
            int i2 = si[tid + s];
            if (v2 > sv[tid] || (v2 == sv[tid] && i2 < si[tid])) {
                sv[tid] = v2;
                si[tid] = i2;
            }
        }
        __syncthreads();
    }
    if (tid == 0) {
        float mv = sv[0];
        int idx = si[0];
        int valid = (mv != 0.0f) ? 1 : 0;
        int c = idx / NPIX, rem = idx % NPIX, h = rem / W2, w = rem % W2;
        if (valid) {
            out_win[3 * k + 0] = (float)c;
            out_win[3 * k + 1] = (float)h;
            out_win[3 * k + 2] = (float)w;
        } else {
            out_win[3 * k + 0] = -1.0f;
            out_win[3 * k + 1] = -1.0f;
            out_win[3 * k + 2] = -1.0f;
        }
        wc = c; wh = h; ww = w; wvalid = valid;
    }
    __syncthreads();
    if (wvalid) {
        for (int i = tid; i < NPIX; i += 256) g_total[wc * NPIX + i] = 0.0f;  // whole channel
        for (int chn = tid; chn < OC2; chn += 256) {                          // 3x3 nbhd, all ch
#pragma unroll
            for (int dy = -1; dy <= 1; dy++)
#pragma unroll
                for (int dx = -1; dx <= 1; dx++) {
                    int hh = wh + dy, wx = ww + dx;
                    if (hh >= 0 && hh < H2 && wx >= 0 && wx < W2)
                        g_total[chn * NPIX + hh * W2 + wx] = 0.0f;
                }
        }
    }
}

// ---------------- launch --------------------------------------------------------
extern "C" void kernel_launch(void* const* d_in, const int* in_sizes, int n_in,
                              void* d_out, int out_size) {
    (void)in_sizes; (void)n_in; (void)out_size;
    const float* x  = (const float*)d_in[0];
    const float* w1 = (const float*)d_in[1];
    const float* w2 = (const float*)d_in[2];

    float* out      = (float*)d_out;
    float* out_spk  = out;
    float* out_pot  = out + (size_t)NOUT1;
    float* out_win  = out + 2 * (size_t)NOUT1;

    zero_kernel<<<(NSP + 255) / 256, 256>>>();
    conv1_kernel<<<dim3(64, 3, 15), dim3(32, 8)>>>(x, w1);
    conv2_kernel<<<dim3(16, 25, 15), dim3(32, 8)>>>(w2, out_pot);
    inh_a_kernel<<<(T_STEPS * NPIX) / 256, 256>>>(out_pot);
    inh_b_kernel<<<NPIX / 256, 256>>>();
    apply_kernel<<<NOUT1 / 256, 256>>>(out_pot, out_spk);
    stats_kernel<<<NCHW / 256, 256>>>(out_pot);
    total_kernel<<<NCHW / 256, 256>>>();
    for (int k = 0; k < 8; k++) {
        argmax1_kernel<<<NPART, 256>>>();
        argmax2_kernel<<<1, 256>>>(out_win, k);
    }
}